// round 1
// baseline (speedup 1.0000x reference)
#include <cuda_runtime.h>
#include <math.h>

#define BB 64
#define LL 1024
#define DD 256
#define CC 256
#define TWO_D 512
#define HD 1280   // 4*D + C

// ---------------- scratch (device globals; no runtime allocation) ----------------
__device__ float g_LIS[BB * LL * TWO_D];            // [B*L, 512]  (qe | ce)
__device__ float g_P[(size_t)BB * LL * LL];         // [B, L, L]   scores -> probs (in place)
__device__ float g_HRP[BB * LL * TWO_D];            // [B*L, 512]
__device__ float g_T[BB * LL * TWO_D];              // [B*L, 512]  MLP pre-GLU (bias added)
__device__ float g_x[BB * LL * DD];                 // [B*L, 256]  running activation
__device__ float g_co[BB * LL * TWO_D];             // [B*L, 512]  conv pre-GLU

__device__ __forceinline__ float sigmoidf_(float v) { return 1.f / (1.f + expf(-v)); }

// ---------------- K1: embedding gather -> LIS ----------------
__global__ __launch_bounds__(256) void k_embed(const int* __restrict__ q,
                                               const int* __restrict__ c,
                                               const float* __restrict__ Eq,
                                               const float* __restrict__ Ec) {
    int r = blockIdx.x;          // b*L + l
    int d = threadIdx.x;         // 0..255
    int qi = q[r];
    int ci = c[r];
    g_LIS[(size_t)r * TWO_D + d]      = Eq[(size_t)qi * DD + d];
    g_LIS[(size_t)r * TWO_D + DD + d] = Ec[(size_t)ci * DD + d];
}

// ---------------- K2: causal scores S[b,i,j] = qe_i . qe_j  (64x64 tiles) ----------------
__global__ __launch_bounds__(256) void k_scores() {
    int jt = blockIdx.x, it = blockIdx.y, b = blockIdx.z;
    if (jt > it) return;
    __shared__ float As[16][68];
    __shared__ float Bs[16][68];
    int tid = threadIdx.x;
    int tx = tid & 15, ty = tid >> 4;
    int ka = tid & 15, ra = tid >> 4;
    float acc[4][4] = {};
    const float* qe = g_LIS + (size_t)b * LL * TWO_D;   // rows stride 512, first 256 = qe
    int i0 = it * 64, j0 = jt * 64;
    for (int k0 = 0; k0 < DD; k0 += 16) {
#pragma unroll
        for (int e = 0; e < 4; e++) {
            int row = ra + e * 16;
            As[ka][row] = qe[(size_t)(i0 + row) * TWO_D + k0 + ka];
            Bs[ka][row] = qe[(size_t)(j0 + row) * TWO_D + k0 + ka];
        }
        __syncthreads();
#pragma unroll
        for (int kk = 0; kk < 16; kk++) {
            float a[4], bv[4];
#pragma unroll
            for (int i = 0; i < 4; i++) a[i] = As[kk][ty * 4 + i];
#pragma unroll
            for (int j = 0; j < 4; j++) bv[j] = Bs[kk][tx * 4 + j];
#pragma unroll
            for (int i = 0; i < 4; i++)
#pragma unroll
                for (int j = 0; j < 4; j++) acc[i][j] += a[i] * bv[j];
        }
        __syncthreads();
    }
    float* Pr = g_P + (size_t)b * LL * LL;
#pragma unroll
    for (int i = 0; i < 4; i++)
#pragma unroll
        for (int j = 0; j < 4; j++)
            Pr[(size_t)(i0 + ty * 4 + i) * LL + (j0 + tx * 4 + j)] = acc[i][j];
}

// ---------------- K3: row softmax with diag-drop renorm (exact reference formula) ----------------
__global__ __launch_bounds__(256) void k_softmax() {
    int r = blockIdx.x;              // b*L + i
    int i = r & (LL - 1);
    float* row = g_P + (size_t)r * LL;
    int t = threadIdx.x;
    __shared__ float red[256];
    __shared__ float s_pii;

    float v[4];
    float m = -3.0e38f;
#pragma unroll
    for (int p = 0; p < 4; p++) {
        int j = p * 256 + t;
        v[p] = (j <= i) ? row[j] : -3.0e38f;
        m = fmaxf(m, v[p]);
    }
    red[t] = m;
    __syncthreads();
    for (int s = 128; s > 0; s >>= 1) { if (t < s) red[t] = fmaxf(red[t], red[t + s]); __syncthreads(); }
    float M = red[0];
    __syncthreads();

    float e[4];
    float ssum = 0.f;
#pragma unroll
    for (int p = 0; p < 4; p++) {
        int j = p * 256 + t;
        e[p] = (j <= i) ? expf(v[p] - M) : 0.f;
        ssum += e[p];
        if (j == i) s_pii = e[p];
    }
    red[t] = ssum;
    __syncthreads();
    for (int s = 128; s > 0; s >>= 1) { if (t < s) red[t] += red[t + s]; __syncthreads(); }
    float Sall = red[0];
    // W_j (j<i) = p_j / ((Sall - p_ii) + 1e-8 * Sall); rows write full length (zeros j>=i)
    float inv = 1.f / ((Sall - s_pii) + 1e-8f * Sall);
#pragma unroll
    for (int p = 0; p < 4; p++) {
        int j = p * 256 + t;
        row[j] = (j < i) ? e[p] * inv : 0.f;
    }
}

// ---------------- shared 128x128x16 GEMM core (8x8 micro-tile) ----------------
#define GEMM_COMPUTE()                                                        \
    do {                                                                      \
        _Pragma("unroll")                                                     \
        for (int kk = 0; kk < 16; kk++) {                                     \
            float a[8], bv[8];                                                \
            _Pragma("unroll")                                                 \
            for (int i = 0; i < 8; i++) a[i] = As[kk][ty * 8 + i];            \
            _Pragma("unroll")                                                 \
            for (int j = 0; j < 8; j++) bv[j] = Bs[kk][tx * 8 + j];           \
            _Pragma("unroll")                                                 \
            for (int i = 0; i < 8; i++)                                       \
                _Pragma("unroll")                                             \
                for (int j = 0; j < 8; j++) acc[i][j] += a[i] * bv[j];        \
        }                                                                     \
    } while (0)

// ---------------- K4: HRP = P @ LIS  (per batch, causal K truncation) ----------------
__global__ __launch_bounds__(256) void k_hrp() {
    int it = blockIdx.x, nt = blockIdx.y, b = blockIdx.z;
    __shared__ float As[16][132];
    __shared__ float Bs[16][132];
    const float* P = g_P + (size_t)b * LL * LL;
    const float* Bsrc = g_LIS + (size_t)b * LL * TWO_D;
    int tid = threadIdx.x;
    int tx = tid & 15, ty = tid >> 4;
    int ka = tid & 15, ra = tid >> 4;
    int nloc = tid & 127, krb = tid >> 7;
    int i0 = it * 128, n0 = nt * 128;
    int kmax = (it + 1) * 128;     // rows above diag are exact zeros (written by softmax)
    float acc[8][8] = {};
    for (int k0 = 0; k0 < kmax; k0 += 16) {
#pragma unroll
        for (int e = 0; e < 8; e++) {
            int row = ra + e * 16;
            As[ka][row] = P[(size_t)(i0 + row) * LL + k0 + ka];
        }
#pragma unroll
        for (int e = 0; e < 8; e++) {
            int kr = krb + e * 2;
            Bs[kr][nloc] = Bsrc[(size_t)(k0 + kr) * TWO_D + n0 + nloc];
        }
        __syncthreads();
        GEMM_COMPUTE();
        __syncthreads();
    }
    float* O = g_HRP + (size_t)b * LL * TWO_D;
#pragma unroll
    for (int i = 0; i < 8; i++)
#pragma unroll
        for (int j = 0; j < 8; j++)
            O[(size_t)(i0 + ty * 8 + i) * TWO_D + n0 + tx * 8 + j] = acc[i][j];
}

// ---------------- K5: fused MLP GEMM: T = H @ [W1;W2]^T + [b1;b2] ----------------
// H row r = [ LIS[r,0:512] | HRP[r,0:512] | cqc[r,0:256] ]  (never materialized)
__global__ __launch_bounds__(256) void k_mlp(const float* __restrict__ cqc,
                                             const float* __restrict__ W1w,
                                             const float* __restrict__ W1b,
                                             const float* __restrict__ W2w,
                                             const float* __restrict__ W2b) {
    int mt = blockIdx.x, nt = blockIdx.y;
    __shared__ float As[16][132];
    __shared__ float Bs[16][132];
    int tid = threadIdx.x;
    int tx = tid & 15, ty = tid >> 4;
    int ka = tid & 15, ra = tid >> 4;
    int kb = tid & 15, nb = tid >> 4;
    int r0 = mt * 128, n0 = nt * 128;
    float acc[8][8] = {};
    for (int k0 = 0; k0 < HD; k0 += 16) {
        const float* asrc;
        int lda;
        if (k0 < 512)       { asrc = g_LIS + k0;          lda = TWO_D; }
        else if (k0 < 1024) { asrc = g_HRP + (k0 - 512);  lda = TWO_D; }
        else                { asrc = cqc   + (k0 - 1024); lda = DD;    }
#pragma unroll
        for (int e = 0; e < 8; e++) {
            int row = ra + e * 16;
            As[ka][row] = asrc[(size_t)(r0 + row) * lda + ka];
        }
#pragma unroll
        for (int e = 0; e < 8; e++) {
            int n = n0 + nb + e * 16;
            float w = (n < 256) ? W1w[(size_t)n * HD + k0 + kb]
                                : W2w[(size_t)(n - 256) * HD + k0 + kb];
            Bs[kb][nb + e * 16] = w;
        }
        __syncthreads();
        GEMM_COMPUTE();
        __syncthreads();
    }
#pragma unroll
    for (int i = 0; i < 8; i++)
#pragma unroll
        for (int j = 0; j < 8; j++) {
            int n = n0 + tx * 8 + j;
            float bias = (n < 256) ? W1b[n] : W2b[n - 256];
            g_T[(size_t)(r0 + ty * 8 + i) * TWO_D + n] = acc[i][j] + bias;
        }
}

// ---------------- K6: GLU: x0 = T[:, :256] * sigmoid(T[:, 256:]) ----------------
__global__ __launch_bounds__(256) void k_glu0() {
    int r = blockIdx.x;
    int d = threadIdx.x;
    float a = g_T[(size_t)r * TWO_D + d];
    float g = g_T[(size_t)r * TWO_D + DD + d];
    g_x[(size_t)r * DD + d] = a * sigmoidf_(g);
}

// ---------------- K7: causal conv as GEMM: co = sum_tap x[l+tap-3] @ w[tap] + b ----------------
__global__ __launch_bounds__(256) void k_conv(const float* __restrict__ w,
                                              const float* __restrict__ bias) {
    int lt = blockIdx.x, nt = blockIdx.y, b = blockIdx.z;
    __shared__ float As[16][132];
    __shared__ float Bs[16][132];
    const float* xb = g_x + (size_t)b * LL * DD;
    int tid = threadIdx.x;
    int tx = tid & 15, ty = tid >> 4;
    int ka = tid & 15, ra = tid >> 4;
    int nloc = tid & 127, krb = tid >> 7;
    int n0 = nt * 128;
    float acc[8][8] = {};
    for (int tap = 0; tap < 4; tap++) {
        int shift = tap - 3;     // in [-3, 0]
        for (int d0 = 0; d0 < DD; d0 += 16) {
#pragma unroll
            for (int e = 0; e < 8; e++) {
                int row = ra + e * 16;
                int lsrc = lt * 128 + row + shift;
                As[ka][row] = (lsrc >= 0) ? xb[(size_t)lsrc * DD + d0 + ka] : 0.f;
            }
#pragma unroll
            for (int e = 0; e < 8; e++) {
                int kr = krb + e * 2;
                Bs[kr][nloc] = w[(size_t)(tap * DD + d0 + kr) * TWO_D + n0 + nloc];
            }
            __syncthreads();
            GEMM_COMPUTE();
            __syncthreads();
        }
    }
    float* O = g_co + (size_t)b * LL * TWO_D;
#pragma unroll
    for (int i = 0; i < 8; i++)
#pragma unroll
        for (int j = 0; j < 8; j++) {
            int n = n0 + tx * 8 + j;
            O[(size_t)(lt * 128 + ty * 8 + i) * TWO_D + n] = acc[i][j] + bias[n];
        }
}

// ---------------- K8: GLU + residual: x = a*sigmoid(g) + x ----------------
__global__ __launch_bounds__(256) void k_glu_res() {
    int r = blockIdx.x;
    int d = threadIdx.x;
    float a = g_co[(size_t)r * TWO_D + d];
    float g = g_co[(size_t)r * TWO_D + DD + d];
    g_x[(size_t)r * DD + d] = a * sigmoidf_(g) + g_x[(size_t)r * DD + d];
}

// ---------------- K9: predict[b,l] = sigmoid( x[b,l] . qe[b,l+1] ) ----------------
__global__ __launch_bounds__(256) void k_predict(float* __restrict__ out) {
    int warp = threadIdx.x >> 5;
    int lane = threadIdx.x & 31;
    int o = blockIdx.x * 8 + warp;
    if (o >= BB * (LL - 1)) return;
    int b = o / (LL - 1), l = o % (LL - 1);
    const float* xr = g_x + (size_t)(b * LL + l) * DD;
    const float* qr = g_LIS + (size_t)(b * LL + l + 1) * TWO_D;   // qe half
    float s = 0.f;
    for (int d = lane; d < DD; d += 32) s += xr[d] * qr[d];
#pragma unroll
    for (int off = 16; off > 0; off >>= 1) s += __shfl_down_sync(0xffffffffu, s, off);
    if (lane == 0) out[o] = sigmoidf_(s);
}

// ---------------- launch ----------------
extern "C" void kernel_launch(void* const* d_in, const int* in_sizes, int n_in,
                              void* d_out, int out_size) {
    (void)in_sizes; (void)n_in; (void)out_size;
    const int*   q     = (const int*)d_in[0];
    const int*   c     = (const int*)d_in[1];
    const float* cqc   = (const float*)d_in[2];
    const float* Eq    = (const float*)d_in[3];
    const float* Ec    = (const float*)d_in[4];
    const float* W1w   = (const float*)d_in[5];
    const float* W1b   = (const float*)d_in[6];
    const float* W2w   = (const float*)d_in[7];
    const float* W2b   = (const float*)d_in[8];
    const float* convw = (const float*)d_in[9];
    const float* convb = (const float*)d_in[10];
    float* out = (float*)d_out;

    k_embed<<<BB * LL, 256>>>(q, c, Eq, Ec);
    k_scores<<<dim3(16, 16, BB), 256>>>();
    k_softmax<<<BB * LL, 256>>>();
    k_hrp<<<dim3(8, 4, BB), 256>>>();
    k_mlp<<<dim3(512, 4), 256>>>(cqc, W1w, W1b, W2w, W2b);
    k_glu0<<<BB * LL, 256>>>();
    for (int l = 0; l < 3; l++) {
        k_conv<<<dim3(8, 4, BB), 256>>>(convw + (size_t)l * 4 * DD * TWO_D,
                                        convb + (size_t)l * TWO_D);
        k_glu_res<<<BB * LL, 256>>>();
    }
    k_predict<<<(BB * (LL - 1) + 7) / 8, 256>>>(out);
}

// round 2
// speedup vs baseline: 4.6255x; 4.6255x over previous
#include <cuda_runtime.h>
#include <cuda_bf16.h>
#include <math.h>
#include <stdint.h>

#define BB 64
#define LL 1024
#define DD 256
#define TWO_D 512
#define HD 1280

typedef __nv_bfloat16 bf16;
typedef __nv_bfloat162 bf162;

// ---------------- scratch (device globals) ----------------
__device__ bf16 g_LIS[(size_t)BB * LL * TWO_D];      // [B*L][512] (qe|ce) bf16
__device__ bf16 g_S[(size_t)BB * LL * LL];           // [B][L][L] scores -> probs (in place)
__device__ bf16 g_HRP[(size_t)BB * LL * TWO_D];
__device__ bf16 g_T[(size_t)BB * LL * TWO_D];
__device__ bf16 g_x[(size_t)BB * LL * DD];
__device__ bf16 g_co[(size_t)BB * LL * TWO_D];
__device__ bf16 g_cqc[(size_t)BB * LL * DD];
__device__ bf16 g_Wmlp[(size_t)TWO_D * HD];          // [n=512][k=1280]
__device__ float g_bmlp[TWO_D];
__device__ bf16 g_convw[(size_t)3 * 1024 * TWO_D];   // [l][k=1024][n=512]

__device__ __forceinline__ float sigmoidf_(float v) { return 1.f / (1.f + __expf(-v)); }

__device__ __forceinline__ float expp(float x) {
    // degree-5 Taylor (|x| small for this model); guarded fallback
    float e = fmaf(x, 0.00833333f, 0.04166667f);
    e = fmaf(x, e, 0.16666667f);
    e = fmaf(x, e, 0.5f);
    e = fmaf(x, e, 1.0f);
    e = fmaf(x, e, 1.0f);
    if (x < -0.5f) e = __expf(x);
    return e;
}

// ---------------- mma helpers ----------------
__device__ __forceinline__ void mma_bf16(float* c, const uint32_t* a, const uint32_t* b) {
    asm volatile(
        "mma.sync.aligned.m16n8k16.row.col.f32.bf16.bf16.f32 "
        "{%0,%1,%2,%3}, {%4,%5,%6,%7}, {%8,%9}, {%0,%1,%2,%3};"
        : "+f"(c[0]), "+f"(c[1]), "+f"(c[2]), "+f"(c[3])
        : "r"(a[0]), "r"(a[1]), "r"(a[2]), "r"(a[3]), "r"(b[0]), "r"(b[1]));
}

// Compute one Kstep=32 for a 128x128 CTA tile. 8 warps: wm=warp>>1 (4), wn=warp&1 (2).
// As: [128][40] bf16 (m-major).  Bs: BT ? [32][136] (k-major) : [128][40] (n-major).
template <bool BT>
__device__ __forceinline__ void warp_k32(const bf16* As, const bf16* Bs,
                                         float acc[16][4], int wm, int wn, int lane) {
#pragma unroll
    for (int ks = 0; ks < 32; ks += 16) {
        uint32_t a[2][4];
#pragma unroll
        for (int t = 0; t < 2; t++) {
            const bf16* p = As + (wm * 32 + t * 16 + ((lane >> 3) & 1) * 8 + (lane & 7)) * 40
                            + ks + (lane >> 4) * 8;
            uint32_t ad = (uint32_t)__cvta_generic_to_shared(p);
            asm volatile("ldmatrix.sync.aligned.m8n8.x4.shared.b16 {%0,%1,%2,%3},[%4];"
                         : "=r"(a[t][0]), "=r"(a[t][1]), "=r"(a[t][2]), "=r"(a[t][3])
                         : "r"(ad));
        }
        uint32_t b[8][2];
#pragma unroll
        for (int p4 = 0; p4 < 4; p4++) {
            uint32_t r0, r1, r2, r3;
            if (BT) {
                const bf16* p = Bs + (ks + ((lane >> 3) & 1) * 8 + (lane & 7)) * 136
                                + wn * 64 + p4 * 16 + (lane >> 4) * 8;
                uint32_t ad = (uint32_t)__cvta_generic_to_shared(p);
                asm volatile("ldmatrix.sync.aligned.m8n8.x4.trans.shared.b16 {%0,%1,%2,%3},[%4];"
                             : "=r"(r0), "=r"(r1), "=r"(r2), "=r"(r3) : "r"(ad));
            } else {
                const bf16* p = Bs + (wn * 64 + p4 * 16 + (lane >> 4) * 8 + (lane & 7)) * 40
                                + ks + ((lane >> 3) & 1) * 8;
                uint32_t ad = (uint32_t)__cvta_generic_to_shared(p);
                asm volatile("ldmatrix.sync.aligned.m8n8.x4.shared.b16 {%0,%1,%2,%3},[%4];"
                             : "=r"(r0), "=r"(r1), "=r"(r2), "=r"(r3) : "r"(ad));
            }
            b[2 * p4][0] = r0; b[2 * p4][1] = r1;
            b[2 * p4 + 1][0] = r2; b[2 * p4 + 1][1] = r3;
        }
#pragma unroll
        for (int t = 0; t < 2; t++)
#pragma unroll
            for (int j = 0; j < 8; j++)
                mma_bf16(acc[t * 8 + j], a[t], b[j]);
    }
}

// loaders: 256 threads copy one tile
__device__ __forceinline__ void ld_tile_mk(bf16* S, const bf16* g, int stride, int tid) {
    int row = tid >> 1, h = tid & 1;
    const bf16* src = g + (size_t)row * stride + h * 16;
    bf16* dst = S + row * 40 + h * 16;
    *(uint4*)dst = *(const uint4*)src;
    *(uint4*)(dst + 8) = *(const uint4*)(src + 8);
}
__device__ __forceinline__ void ld_tile_kn(bf16* S, const bf16* g, int stride, int tid) {
    int row = tid >> 3, c = tid & 7;
    const bf16* src = g + (size_t)row * stride + c * 16;
    bf16* dst = S + row * 136 + c * 16;
    *(uint4*)dst = *(const uint4*)src;
    *(uint4*)(dst + 8) = *(const uint4*)(src + 8);
}

__device__ __forceinline__ void store_tile(bf16* out, size_t ldc, float acc[16][4],
                                           int wm, int wn, int lane, const float* bias) {
#pragma unroll
    for (int t = 0; t < 2; t++)
#pragma unroll
        for (int j = 0; j < 8; j++) {
            int r = wm * 32 + t * 16 + (lane >> 2);
            int cc = wn * 64 + j * 8 + (lane & 3) * 2;
            float b0 = 0.f, b1 = 0.f;
            if (bias) { b0 = bias[cc]; b1 = bias[cc + 1]; }
            float* a = acc[t * 8 + j];
            *(bf162*)(out + (size_t)r * ldc + cc) = __floats2bfloat162_rn(a[0] + b0, a[1] + b1);
            *(bf162*)(out + (size_t)(r + 8) * ldc + cc) = __floats2bfloat162_rn(a[2] + b0, a[3] + b1);
        }
}

// ---------------- conversions ----------------
__global__ void k_cvt_wmlp(const float* __restrict__ W1w, const float* __restrict__ W2w) {
    int id = blockIdx.x * 256 + threadIdx.x;
    if (id >= TWO_D * HD) return;
    int n = id / HD, k = id % HD;
    float v = (n < DD) ? W1w[(size_t)n * HD + k] : W2w[(size_t)(n - DD) * HD + k];
    g_Wmlp[id] = __float2bfloat16(v);
}
__global__ void k_cvt_bmlp(const float* __restrict__ b1, const float* __restrict__ b2) {
    int n = threadIdx.x;
    g_bmlp[n] = (n < DD) ? b1[n] : b2[n - DD];
}
__global__ void k_cvt_convw(const float* __restrict__ w) {
    size_t id = (size_t)blockIdx.x * 256 + threadIdx.x;
    if (id >= (size_t)3 * 1024 * TWO_D) return;
    g_convw[id] = __float2bfloat16(w[id]);   // identical flat layout [l][k][n]
}
__global__ void k_cvt_cqc(const float* __restrict__ cqc) {
    size_t id = (size_t)blockIdx.x * 256 + threadIdx.x;
    size_t n4 = (size_t)BB * LL * DD / 4;
    if (id >= n4) return;
    float4 v = ((const float4*)cqc)[id];
    bf162* o = (bf162*)g_cqc;
    o[id * 2] = __floats2bfloat162_rn(v.x, v.y);
    o[id * 2 + 1] = __floats2bfloat162_rn(v.z, v.w);
}

// ---------------- embed ----------------
__global__ __launch_bounds__(256) void k_embed(const int* __restrict__ q,
                                               const int* __restrict__ c,
                                               const float* __restrict__ Eq,
                                               const float* __restrict__ Ec) {
    int r = blockIdx.x, d = threadIdx.x;
    int qi = q[r], ci = c[r];
    g_LIS[(size_t)r * TWO_D + d]      = __float2bfloat16(Eq[(size_t)qi * DD + d]);
    g_LIS[(size_t)r * TWO_D + DD + d] = __float2bfloat16(Ec[(size_t)ci * DD + d]);
}

// ---------------- scores: S = qe qe^T (lower-tri tiles) ----------------
__global__ __launch_bounds__(256, 2) void k_scores() {
    int jt = blockIdx.x, it = blockIdx.y, b = blockIdx.z;
    if (jt > it) return;
    __shared__ alignas(16) bf16 As[128 * 40];
    __shared__ alignas(16) bf16 Bs[128 * 40];
    int tid = threadIdx.x, warp = tid >> 5, lane = tid & 31;
    int wm = warp >> 1, wn = warp & 1;
    const bf16* Ab = g_LIS + ((size_t)b * LL + it * 128) * TWO_D;
    const bf16* Bb = g_LIS + ((size_t)b * LL + jt * 128) * TWO_D;
    float acc[16][4] = {};
    for (int k0 = 0; k0 < DD; k0 += 32) {
        ld_tile_mk(As, Ab + k0, TWO_D, tid);
        ld_tile_mk(Bs, Bb + k0, TWO_D, tid);
        __syncthreads();
        warp_k32<false>(As, Bs, acc, wm, wn, lane);
        __syncthreads();
    }
    bf16* out = g_S + ((size_t)b * LL + it * 128) * LL + jt * 128;
    store_tile(out, LL, acc, wm, wn, lane, nullptr);
}

// ---------------- softmax (warp per row), in place on g_S ----------------
__global__ __launch_bounds__(256) void k_softmax() {
    int warp = threadIdx.x >> 5, lane = threadIdx.x & 31;
    int r = blockIdx.x * 8 + warp;          // b*L + i
    int i = r & (LL - 1);
    bf16* row = g_S + (size_t)r * LL;
    float e[32];
    float m = -3.0e38f;
#pragma unroll
    for (int c = 0; c < 32; c++) {
        int j = c * 32 + lane;
        float v = (j <= i) ? __bfloat162float(row[j]) : -3.0e38f;
        e[c] = v;
        m = fmaxf(m, v);
    }
#pragma unroll
    for (int off = 16; off > 0; off >>= 1)
        m = fmaxf(m, __shfl_xor_sync(0xffffffffu, m, off));
    float ssum = 0.f, pii = 0.f;
#pragma unroll
    for (int c = 0; c < 32; c++) {
        int j = c * 32 + lane;
        float ev = (j <= i) ? expp(e[c] - m) : 0.f;
        e[c] = ev;
        ssum += ev;
        if (j == i) pii = ev;
    }
#pragma unroll
    for (int off = 16; off > 0; off >>= 1) {
        ssum += __shfl_xor_sync(0xffffffffu, ssum, off);
        pii += __shfl_xor_sync(0xffffffffu, pii, off);
    }
    float inv = 1.f / ((ssum - pii) + 1e-8f * ssum);
#pragma unroll
    for (int c = 0; c < 32; c++) {
        int j = c * 32 + lane;
        row[j] = __float2bfloat16((j < i) ? e[c] * inv : 0.f);
    }
}

// ---------------- HRP = P @ LIS (causal K trunc) ----------------
__global__ __launch_bounds__(256, 2) void k_hrp() {
    int nt = blockIdx.x, it = blockIdx.y, b = blockIdx.z;
    __shared__ alignas(16) bf16 As[128 * 40];
    __shared__ alignas(16) bf16 Bs[32 * 136];
    int tid = threadIdx.x, warp = tid >> 5, lane = tid & 31;
    int wm = warp >> 1, wn = warp & 1;
    const bf16* Ab = g_S + ((size_t)b * LL + it * 128) * LL;
    const bf16* Bb = g_LIS + (size_t)b * LL * TWO_D + nt * 128;
    float acc[16][4] = {};
    int kmax = (it + 1) * 128;
    for (int k0 = 0; k0 < kmax; k0 += 32) {
        ld_tile_mk(As, Ab + k0, LL, tid);
        ld_tile_kn(Bs, Bb + (size_t)k0 * TWO_D, TWO_D, tid);
        __syncthreads();
        warp_k32<true>(As, Bs, acc, wm, wn, lane);
        __syncthreads();
    }
    bf16* out = g_HRP + ((size_t)b * LL + it * 128) * TWO_D + nt * 128;
    store_tile(out, TWO_D, acc, wm, wn, lane, nullptr);
}

// ---------------- MLP: T = H @ Wmlp^T + b ----------------
__global__ __launch_bounds__(256, 2) void k_mlp() {
    int nt = blockIdx.x, mt = blockIdx.y;
    __shared__ alignas(16) bf16 As[128 * 40];
    __shared__ alignas(16) bf16 Bs[128 * 40];
    int tid = threadIdx.x, warp = tid >> 5, lane = tid & 31;
    int wm = warp >> 1, wn = warp & 1;
    size_t r0 = (size_t)mt * 128;
    int n0 = nt * 128;
    const bf16* Wb = g_Wmlp + (size_t)n0 * HD;
    float acc[16][4] = {};
    for (int k0 = 0; k0 < HD; k0 += 32) {
        const bf16* a;
        int s;
        if (k0 < 512)       { a = g_LIS + r0 * TWO_D + k0;          s = TWO_D; }
        else if (k0 < 1024) { a = g_HRP + r0 * TWO_D + (k0 - 512);  s = TWO_D; }
        else                { a = g_cqc + r0 * DD + (k0 - 1024);    s = DD; }
        ld_tile_mk(As, a, s, tid);
        ld_tile_mk(Bs, Wb + k0, HD, tid);
        __syncthreads();
        warp_k32<false>(As, Bs, acc, wm, wn, lane);
        __syncthreads();
    }
    bf16* out = g_T + r0 * TWO_D + n0;
    store_tile(out, TWO_D, acc, wm, wn, lane, g_bmlp + n0);
}

// ---------------- GLU ----------------
__global__ __launch_bounds__(256) void k_glu0() {
    size_t r = blockIdx.x;
    int d = threadIdx.x;
    float a = __bfloat162float(g_T[r * TWO_D + d]);
    float g = __bfloat162float(g_T[r * TWO_D + DD + d]);
    g_x[r * DD + d] = __float2bfloat16(a * sigmoidf_(g));
}

// ---------------- conv layer (GEMM over k = tap*256 + d) ----------------
__global__ __launch_bounds__(256, 2) void k_conv(int l, const float* __restrict__ cb) {
    int nt = blockIdx.x, lt = blockIdx.y, b = blockIdx.z;
    __shared__ alignas(16) bf16 As[128 * 40];
    __shared__ alignas(16) bf16 Bs[32 * 136];
    int tid = threadIdx.x, warp = tid >> 5, lane = tid & 31;
    int wm = warp >> 1, wn = warp & 1;
    int n0 = nt * 128;
    const bf16* Wb = g_convw + (size_t)l * 1024 * TWO_D + n0;
    const bf16* xb = g_x + (size_t)b * LL * DD;
    float acc[16][4] = {};
    int arow = tid >> 1, ah = tid & 1;
    for (int k0 = 0; k0 < 1024; k0 += 32) {
        int tap = k0 >> 8;
        int lidx = lt * 128 + arow + tap - 3;
        bf16* dst = As + arow * 40 + ah * 16;
        if (lidx >= 0) {
            const bf16* src = xb + (size_t)lidx * DD + (k0 & 255) + ah * 16;
            *(uint4*)dst = *(const uint4*)src;
            *(uint4*)(dst + 8) = *(const uint4*)(src + 8);
        } else {
            uint4 z = {0, 0, 0, 0};
            *(uint4*)dst = z;
            *(uint4*)(dst + 8) = z;
        }
        ld_tile_kn(Bs, Wb + (size_t)k0 * TWO_D, TWO_D, tid);
        __syncthreads();
        warp_k32<true>(As, Bs, acc, wm, wn, lane);
        __syncthreads();
    }
    bf16* out = g_co + ((size_t)b * LL + lt * 128) * TWO_D + n0;
    store_tile(out, TWO_D, acc, wm, wn, lane, cb + n0);
}

__global__ __launch_bounds__(256) void k_glu_res() {
    size_t r = blockIdx.x;
    int d = threadIdx.x;
    float a = __bfloat162float(g_co[r * TWO_D + d]);
    float g = __bfloat162float(g_co[r * TWO_D + DD + d]);
    float x = __bfloat162float(g_x[r * DD + d]);
    g_x[r * DD + d] = __float2bfloat16(a * sigmoidf_(g) + x);
}

// ---------------- predict ----------------
__global__ __launch_bounds__(256) void k_predict(float* __restrict__ out) {
    int warp = threadIdx.x >> 5, lane = threadIdx.x & 31;
    int o = blockIdx.x * 8 + warp;
    if (o >= BB * (LL - 1)) return;
    int b = o / (LL - 1), l = o % (LL - 1);
    const bf16* xr = g_x + (size_t)(b * LL + l) * DD;
    const bf16* qr = g_LIS + (size_t)(b * LL + l + 1) * TWO_D;
    float s = 0.f;
    for (int d = lane; d < DD; d += 32)
        s += __bfloat162float(xr[d]) * __bfloat162float(qr[d]);
#pragma unroll
    for (int off = 16; off > 0; off >>= 1) s += __shfl_down_sync(0xffffffffu, s, off);
    if (lane == 0) out[o] = sigmoidf_(s);
}

// ---------------- launch ----------------
extern "C" void kernel_launch(void* const* d_in, const int* in_sizes, int n_in,
                              void* d_out, int out_size) {
    (void)in_sizes; (void)n_in; (void)out_size;
    const int*   q     = (const int*)d_in[0];
    const int*   c     = (const int*)d_in[1];
    const float* cqc   = (const float*)d_in[2];
    const float* Eq    = (const float*)d_in[3];
    const float* Ec    = (const float*)d_in[4];
    const float* W1w   = (const float*)d_in[5];
    const float* W1b   = (const float*)d_in[6];
    const float* W2w   = (const float*)d_in[7];
    const float* W2b   = (const float*)d_in[8];
    const float* convw = (const float*)d_in[9];
    const float* convb = (const float*)d_in[10];
    float* out = (float*)d_out;

    k_cvt_wmlp<<<(TWO_D * HD + 255) / 256, 256>>>(W1w, W2w);
    k_cvt_bmlp<<<1, 512>>>(W1b, W2b);
    k_cvt_convw<<<(3 * 1024 * TWO_D + 255) / 256, 256>>>(convw);
    k_cvt_cqc<<<(BB * LL * DD / 4 + 255) / 256, 256>>>(cqc);
    k_embed<<<BB * LL, 256>>>(q, c, Eq, Ec);

    k_scores<<<dim3(8, 8, BB), 256>>>();
    k_softmax<<<BB * LL / 8, 256>>>();
    k_hrp<<<dim3(4, 8, BB), 256>>>();
    k_mlp<<<dim3(4, 512), 256>>>();
    k_glu0<<<BB * LL, 256>>>();
    for (int l = 0; l < 3; l++) {
        k_conv<<<dim3(4, 8, BB), 256>>>(l, convb + (size_t)l * TWO_D);
        k_glu_res<<<BB * LL, 256>>>();
    }
    k_predict<<<(BB * (LL - 1) + 7) / 8, 256>>>(out);
}

// round 4
// speedup vs baseline: 5.7536x; 1.2439x over previous
#include <cuda_runtime.h>
#include <cuda_bf16.h>
#include <math.h>
#include <stdint.h>

#define BB 64
#define LL 1024
#define DD 256
#define TWO_D 512
#define HD 1280

typedef __nv_bfloat16 bf16;
typedef __nv_bfloat162 bf162;

// ---------------- scratch (device globals) ----------------
__device__ bf16 g_LIS[(size_t)BB * LL * TWO_D];      // [B*L][512] (qe|ce)
__device__ bf16 g_S[(size_t)BB * LL * LL];           // [B][L][L]
__device__ bf16 g_HRP[(size_t)BB * LL * TWO_D];
__device__ bf16 g_T[(size_t)BB * LL * TWO_D];
__device__ bf16 g_x[(size_t)BB * LL * DD];
__device__ bf16 g_co[(size_t)BB * LL * TWO_D];
__device__ bf16 g_cqc[(size_t)BB * LL * DD];
__device__ bf16 g_Wmlp[(size_t)TWO_D * HD];          // [n=512][k=1280]
__device__ float g_bmlp[TWO_D];
__device__ bf16 g_convw[(size_t)3 * 1024 * TWO_D];   // [l][k=1024][n=512]

__device__ __forceinline__ float sigmoidf_(float v) { return 1.f / (1.f + __expf(-v)); }

__device__ __forceinline__ float expp(float x) {
    float e = fmaf(x, 0.00833333f, 0.04166667f);
    e = fmaf(x, e, 0.16666667f);
    e = fmaf(x, e, 0.5f);
    e = fmaf(x, e, 1.0f);
    e = fmaf(x, e, 1.0f);
    if (x < -0.5f) e = __expf(x);
    return e;
}

// ---------------- async copy helpers ----------------
__device__ __forceinline__ uint32_t s2u(const void* p) {
    return (uint32_t)__cvta_generic_to_shared(p);
}
__device__ __forceinline__ void cp16(char* dst, const void* src, bool v) {
    asm volatile("cp.async.cg.shared.global [%0], [%1], 16, %2;"
                 :: "r"(s2u(dst)), "l"(src), "r"(v ? 16 : 0));
}
#define CP_COMMIT() asm volatile("cp.async.commit_group;" ::: "memory")

// ---------------- mma ----------------
__device__ __forceinline__ void mma_bf16(float* c, const uint32_t* a, const uint32_t* b) {
    asm volatile(
        "mma.sync.aligned.m16n8k16.row.col.f32.bf16.bf16.f32 "
        "{%0,%1,%2,%3}, {%4,%5,%6,%7}, {%8,%9}, {%0,%1,%2,%3};"
        : "+f"(c[0]), "+f"(c[1]), "+f"(c[2]), "+f"(c[3])
        : "r"(a[0]), "r"(a[1]), "r"(a[2]), "r"(a[3]), "r"(b[0]), "r"(b[1]));
}

// ---------------- swizzle ----------------
// mk tiles: rows of 128B (64 bf16). SW128: bits[6:4] ^= bits[9:7] (row%8).
__device__ __forceinline__ uint32_t swz128(uint32_t off) {
    return off ^ ((off >> 3) & 0x70);
}
// kn tiles: rows of 256B (128 bf16). conflict-free: unit ^= row%8 within each 128B half.
__device__ __forceinline__ uint32_t swzkn(uint32_t row, uint32_t cb) {
    uint32_t unit = (cb >> 4) & 7;
    return row * 256 + (cb & 0x80) + ((unit ^ (row & 7)) << 4) + (cb & 15);
}

// ---------------- compute one K=64 chunk (128x128 CTA tile, 8 warps 4x2) ----------------
// As: 128 rows x 128B swz128.  Bs: BT ? 64 k-rows x 256B swzkn : 128 n-rows x 128B swz128.
template <bool BT>
__device__ __forceinline__ void warp_k64(const char* As, const char* Bs,
                                         float acc[16][4], int wm, int wn, int lane) {
    uint32_t abase = s2u(As), bbase = s2u(Bs);
#pragma unroll
    for (int ks = 0; ks < 64; ks += 16) {
        uint32_t a[2][4];
#pragma unroll
        for (int t = 0; t < 2; t++) {
            uint32_t row = wm * 32 + t * 16 + ((lane >> 3) & 1) * 8 + (lane & 7);
            uint32_t cb = (ks + (lane >> 4) * 8) * 2;
            uint32_t ad = abase + swz128(row * 128 + cb);
            asm volatile("ldmatrix.sync.aligned.m8n8.x4.shared.b16 {%0,%1,%2,%3},[%4];"
                         : "=r"(a[t][0]), "=r"(a[t][1]), "=r"(a[t][2]), "=r"(a[t][3])
                         : "r"(ad));
        }
        uint32_t b[8][2];
#pragma unroll
        for (int p4 = 0; p4 < 4; p4++) {
            uint32_t r0, r1, r2, r3;
            if (BT) {
                uint32_t row = ks + ((lane >> 3) & 1) * 8 + (lane & 7);
                uint32_t cb = (wn * 64 + p4 * 16 + (lane >> 4) * 8) * 2;
                uint32_t ad = bbase + swzkn(row, cb);
                asm volatile("ldmatrix.sync.aligned.m8n8.x4.trans.shared.b16 {%0,%1,%2,%3},[%4];"
                             : "=r"(r0), "=r"(r1), "=r"(r2), "=r"(r3) : "r"(ad));
            } else {
                uint32_t row = wn * 64 + p4 * 16 + (lane >> 4) * 8 + (lane & 7);
                uint32_t cb = (ks + ((lane >> 3) & 1) * 8) * 2;
                uint32_t ad = bbase + swz128(row * 128 + cb);
                asm volatile("ldmatrix.sync.aligned.m8n8.x4.shared.b16 {%0,%1,%2,%3},[%4];"
                             : "=r"(r0), "=r"(r1), "=r"(r2), "=r"(r3) : "r"(ad));
            }
            b[2 * p4][0] = r0; b[2 * p4][1] = r1;
            b[2 * p4 + 1][0] = r2; b[2 * p4 + 1][1] = r3;
        }
#pragma unroll
        for (int t = 0; t < 2; t++)
#pragma unroll
            for (int j = 0; j < 8; j++)
                mma_bf16(acc[t * 8 + j], a[t], b[j]);
    }
}

__device__ __forceinline__ void store_tile(bf16* out, size_t ldc, float acc[16][4],
                                           int wm, int wn, int lane, const float* bias) {
#pragma unroll
    for (int t = 0; t < 2; t++)
#pragma unroll
        for (int j = 0; j < 8; j++) {
            int r = wm * 32 + t * 16 + (lane >> 2);
            int cc = wn * 64 + j * 8 + (lane & 3) * 2;
            float b0 = 0.f, b1 = 0.f;
            if (bias) { b0 = bias[cc]; b1 = bias[cc + 1]; }
            float* a = acc[t * 8 + j];
            *(bf162*)(out + (size_t)r * ldc + cc) = __floats2bfloat162_rn(a[0] + b0, a[1] + b1);
            *(bf162*)(out + (size_t)(r + 8) * ldc + cc) = __floats2bfloat162_rn(a[2] + b0, a[3] + b1);
        }
}

// ---------------- pipelined GEMM kernel ----------------
// MODE 0=scores 1=hrp 2=mlp 3=conv.  CTA tile 128(M)x128(N), K chunk 64, 3 stages.
#define STAGE_BYTES 16384
#define B_SMEM_OFF  (3 * 16384)
#define SMEM_TOTAL  (6 * 16384)

template <int MODE>
__device__ __forceinline__ void load_chunk(char* smem, int s, int k0, int tid,
                                           int bx, int by, int bz, int layer) {
    char* Ab = smem + s * STAGE_BYTES;
    char* Bb = smem + B_SMEM_OFF + s * STAGE_BYTES;
    // ---- A: 128 rows x 64 els ----
    {
        int row = tid >> 1, h = tid & 1;
        const bf16* src; bool v = true;
        if (MODE == 0) {
            src = g_LIS + ((size_t)(bz * LL + by * 128 + row) * TWO_D + k0);
        } else if (MODE == 1) {
            src = g_S + ((size_t)(bz * LL + by * 128 + row) * LL + k0);
        } else if (MODE == 2) {
            int r = by * 128 + row;
            if (k0 < 512)       src = g_LIS + ((size_t)r * TWO_D + k0);
            else if (k0 < 1024) src = g_HRP + ((size_t)r * TWO_D + (k0 - 512));
            else                src = g_cqc + ((size_t)r * DD + (k0 - 1024));
        } else {
            int ls = by * 128 + row + (k0 >> 8) - 3;
            v = (ls >= 0); if (!v) ls = 0;
            src = g_x + ((size_t)(bz * LL + ls) * DD + (k0 & 255));
        }
#pragma unroll
        for (int j = 0; j < 4; j++) {
            uint32_t cb = h * 64 + j * 16;
            cp16(Ab + swz128((uint32_t)row * 128 + cb), src + cb / 2, v);
        }
    }
    // ---- B ----
    if (MODE == 0 || MODE == 2) {       // mk layout: 128 n-rows x 64 els
        int row = tid >> 1, h = tid & 1;
        const bf16* src;
        if (MODE == 0) src = g_LIS + ((size_t)(bz * LL + bx * 128 + row) * TWO_D + k0);
        else           src = g_Wmlp + ((size_t)(bx * 128 + row) * HD + k0);
#pragma unroll
        for (int j = 0; j < 4; j++) {
            uint32_t cb = h * 64 + j * 16;
            cp16(Bb + swz128((uint32_t)row * 128 + cb), src + cb / 2, true);
        }
    } else {                            // kn layout: 64 k-rows x 128 els
        int row = tid >> 2, q = tid & 3;
        const bf16* src;
        if (MODE == 1) src = g_LIS + ((size_t)(bz * LL + k0 + row) * TWO_D + bx * 128);
        else           src = g_convw + ((size_t)(layer * 1024 + k0 + row)) * TWO_D + bx * 128;
#pragma unroll
        for (int j = 0; j < 4; j++) {
            uint32_t cb = q * 64 + j * 16;
            cp16(Bb + swzkn((uint32_t)row, cb), src + cb / 2, true);
        }
    }
}

template <int MODE>
__global__ void __launch_bounds__(256, 2) k_gemm(const float* __restrict__ bias_in, int layer) {
    extern __shared__ char smem[];
    int tid = threadIdx.x, wid = tid >> 5, lane = tid & 31;
    int bx = blockIdx.x, by = blockIdx.y, bz = blockIdx.z;
    if (MODE == 0 && bx > by) return;                 // strictly above diagonal
    int nch = (MODE == 0) ? 4 : (MODE == 1) ? (by + 1) * 2 : (MODE == 2) ? 20 : 16;
    int wm = wid >> 1, wn = wid & 1;

    float acc[16][4] = {};

    load_chunk<MODE>(smem, 0, 0, tid, bx, by, bz, layer);  CP_COMMIT();
    load_chunk<MODE>(smem, 1, 64, tid, bx, by, bz, layer); CP_COMMIT();

    const bool BT = (MODE == 1 || MODE == 3);
#pragma unroll 1
    for (int i = 0; i < nch; i++) {
        int s = i % 3;
        if (i == nch - 1) asm volatile("cp.async.wait_group 0;" ::: "memory");
        else              asm volatile("cp.async.wait_group 1;" ::: "memory");
        __syncthreads();
        if (i + 2 < nch) {
            load_chunk<MODE>(smem, (i + 2) % 3, (i + 2) * 64, tid, bx, by, bz, layer);
            CP_COMMIT();
        }
        warp_k64<(MODE == 1 || MODE == 3)>(smem + s * STAGE_BYTES,
                                           smem + B_SMEM_OFF + s * STAGE_BYTES,
                                           acc, wm, wn, lane);
    }
    (void)BT;

    bf16* out; size_t ldc; const float* bias = nullptr;
    if (MODE == 0)      { out = g_S   + ((size_t)(bz * LL + by * 128)) * LL    + bx * 128; ldc = LL; }
    else if (MODE == 1) { out = g_HRP + ((size_t)(bz * LL + by * 128)) * TWO_D + bx * 128; ldc = TWO_D; }
    else if (MODE == 2) { out = g_T   + ((size_t)by * 128) * TWO_D             + bx * 128; ldc = TWO_D; bias = g_bmlp + bx * 128; }
    else                { out = g_co  + ((size_t)(bz * LL + by * 128)) * TWO_D + bx * 128; ldc = TWO_D; bias = bias_in + bx * 128; }
    store_tile(out, ldc, acc, wm, wn, lane, bias);
}

// ---------------- conversions ----------------
__global__ void k_cvt_wmlp(const float* __restrict__ W1w, const float* __restrict__ W2w) {
    int id = blockIdx.x * 256 + threadIdx.x;
    if (id >= TWO_D * HD) return;
    int n = id / HD, k = id % HD;
    float v = (n < DD) ? W1w[(size_t)n * HD + k] : W2w[(size_t)(n - DD) * HD + k];
    g_Wmlp[id] = __float2bfloat16(v);
}
__global__ void k_cvt_bmlp(const float* __restrict__ b1, const float* __restrict__ b2) {
    int n = threadIdx.x;
    g_bmlp[n] = (n < DD) ? b1[n] : b2[n - DD];
}
__global__ void k_cvt_convw(const float* __restrict__ w) {
    size_t id = (size_t)blockIdx.x * 256 + threadIdx.x;
    if (id >= (size_t)3 * 1024 * TWO_D) return;
    g_convw[id] = __float2bfloat16(w[id]);
}
__global__ void k_cvt_cqc(const float* __restrict__ cqc) {
    size_t id = (size_t)blockIdx.x * 256 + threadIdx.x;
    size_t n4 = (size_t)BB * LL * DD / 4;
    if (id >= n4) return;
    float4 v = ((const float4*)cqc)[id];
    bf162* o = (bf162*)g_cqc;
    o[id * 2] = __floats2bfloat162_rn(v.x, v.y);
    o[id * 2 + 1] = __floats2bfloat162_rn(v.z, v.w);
}
__global__ __launch_bounds__(256) void k_embed(const int* __restrict__ q,
                                               const int* __restrict__ c,
                                               const float* __restrict__ Eq,
                                               const float* __restrict__ Ec) {
    int r = blockIdx.x, d = threadIdx.x;
    int qi = q[r], ci = c[r];
    g_LIS[(size_t)r * TWO_D + d]      = __float2bfloat16(Eq[(size_t)qi * DD + d]);
    g_LIS[(size_t)r * TWO_D + DD + d] = __float2bfloat16(Ec[(size_t)ci * DD + d]);
}

// ---------------- softmax (warp per row), in place on g_S ----------------
__global__ __launch_bounds__(256) void k_softmax() {
    int warp = threadIdx.x >> 5, lane = threadIdx.x & 31;
    int r = blockIdx.x * 8 + warp;
    int i = r & (LL - 1);
    bf16* row = g_S + (size_t)r * LL;
    float e[32];
    float m = -3.0e38f;
#pragma unroll
    for (int c = 0; c < 32; c++) {
        int j = c * 32 + lane;
        float v = (j <= i) ? __bfloat162float(row[j]) : -3.0e38f;
        e[c] = v;
        m = fmaxf(m, v);
    }
#pragma unroll
    for (int off = 16; off > 0; off >>= 1)
        m = fmaxf(m, __shfl_xor_sync(0xffffffffu, m, off));
    float ssum = 0.f, pii = 0.f;
#pragma unroll
    for (int c = 0; c < 32; c++) {
        int j = c * 32 + lane;
        float ev = (j <= i) ? expp(e[c] - m) : 0.f;
        e[c] = ev;
        ssum += ev;
        if (j == i) pii = ev;
    }
#pragma unroll
    for (int off = 16; off > 0; off >>= 1) {
        ssum += __shfl_xor_sync(0xffffffffu, ssum, off);
        pii += __shfl_xor_sync(0xffffffffu, pii, off);
    }
    float inv = 1.f / ((ssum - pii) + 1e-8f * ssum);
#pragma unroll
    for (int c = 0; c < 32; c++) {
        int j = c * 32 + lane;
        row[j] = __float2bfloat16((j < i) ? e[c] * inv : 0.f);
    }
}

// ---------------- elementwise ----------------
__global__ __launch_bounds__(256) void k_glu0() {
    size_t r = blockIdx.x;
    int d = threadIdx.x;
    float a = __bfloat162float(g_T[r * TWO_D + d]);
    float g = __bfloat162float(g_T[r * TWO_D + DD + d]);
    g_x[r * DD + d] = __float2bfloat16(a * sigmoidf_(g));
}
__global__ __launch_bounds__(256) void k_glu_res() {
    size_t r = blockIdx.x;
    int d = threadIdx.x;
    float a = __bfloat162float(g_co[r * TWO_D + d]);
    float g = __bfloat162float(g_co[r * TWO_D + DD + d]);
    float x = __bfloat162float(g_x[r * DD + d]);
    g_x[r * DD + d] = __float2bfloat16(a * sigmoidf_(g) + x);
}
__global__ __launch_bounds__(256) void k_predict(float* __restrict__ out) {
    int warp = threadIdx.x >> 5, lane = threadIdx.x & 31;
    int o = blockIdx.x * 8 + warp;
    if (o >= BB * (LL - 1)) return;
    int b = o / (LL - 1), l = o % (LL - 1);
    const bf16* xr = g_x + (size_t)(b * LL + l) * DD;
    const bf16* qr = g_LIS + (size_t)(b * LL + l + 1) * TWO_D;
    float s = 0.f;
    for (int d = lane; d < DD; d += 32)
        s += __bfloat162float(xr[d]) * __bfloat162float(qr[d]);
#pragma unroll
    for (int off = 16; off > 0; off >>= 1) s += __shfl_down_sync(0xffffffffu, s, off);
    if (lane == 0) out[o] = sigmoidf_(s);
}

// ---------------- launch ----------------
extern "C" void kernel_launch(void* const* d_in, const int* in_sizes, int n_in,
                              void* d_out, int out_size) {
    (void)in_sizes; (void)n_in; (void)out_size;
    const int*   q     = (const int*)d_in[0];
    const int*   c     = (const int*)d_in[1];
    const float* cqc   = (const float*)d_in[2];
    const float* Eq    = (const float*)d_in[3];
    const float* Ec    = (const float*)d_in[4];
    const float* W1w   = (const float*)d_in[5];
    const float* W1b   = (const float*)d_in[6];
    const float* W2w   = (const float*)d_in[7];
    const float* W2b   = (const float*)d_in[8];
    const float* convw = (const float*)d_in[9];
    const float* convb = (const float*)d_in[10];
    float* out = (float*)d_out;

    static bool attr_done = false;
    if (!attr_done) {
        cudaFuncSetAttribute(k_gemm<0>, cudaFuncAttributeMaxDynamicSharedMemorySize, SMEM_TOTAL);
        cudaFuncSetAttribute(k_gemm<1>, cudaFuncAttributeMaxDynamicSharedMemorySize, SMEM_TOTAL);
        cudaFuncSetAttribute(k_gemm<2>, cudaFuncAttributeMaxDynamicSharedMemorySize, SMEM_TOTAL);
        cudaFuncSetAttribute(k_gemm<3>, cudaFuncAttributeMaxDynamicSharedMemorySize, SMEM_TOTAL);
        attr_done = true;
    }

    k_cvt_wmlp<<<(TWO_D * HD + 255) / 256, 256>>>(W1w, W2w);
    k_cvt_bmlp<<<1, 512>>>(W1b, W2b);
    k_cvt_convw<<<(3 * 1024 * TWO_D + 255) / 256, 256>>>(convw);
    k_cvt_cqc<<<(BB * LL * DD / 4 + 255) / 256, 256>>>(cqc);
    k_embed<<<BB * LL, 256>>>(q, c, Eq, Ec);

    k_gemm<0><<<dim3(8, 8, BB), 256, SMEM_TOTAL>>>(nullptr, 0);
    k_softmax<<<BB * LL / 8, 256>>>();
    k_gemm<1><<<dim3(4, 8, BB), 256, SMEM_TOTAL>>>(nullptr, 0);
    k_gemm<2><<<dim3(4, 512, 1), 256, SMEM_TOTAL>>>(nullptr, 0);
    k_glu0<<<BB * LL, 256>>>();
    for (int l = 0; l < 3; l++) {
        k_gemm<3><<<dim3(4, 8, BB), 256, SMEM_TOTAL>>>(convb + (size_t)l * TWO_D, l);
        k_glu_res<<<BB * LL, 256>>>();
    }
    k_predict<<<(BB * (LL - 1) + 7) / 8, 256>>>(out);
}